// round 7
// baseline (speedup 1.0000x reference)
#include <cuda_runtime.h>
#include <cuda_fp16.h>
#include <cstdint>

#define BATCH 8192
#define INF   4096
#define OUTF  4096
#define BS    64
#define NBR   64
#define BPR   16
#define TM    256
#define NT_M  (BATCH / TM)          // 32
#define WSTAGES 4
#define XT_BYTES (TM * BS * 2)      // 32768 (fp16 tile)
#define WT_BYTES (BS * BS * 2)      // 8192
#define W_BASE (2 * XT_BYTES)       // 65536 (x double-buffered)
#define SMEM_SZ (W_BASE + WSTAGES * WT_BYTES)   // 98304

// Scratch (device global; allocation-free)
__device__ __half g_wt[(size_t)NBR * BPR * BS * BS];    // fp16 W, [blk][b][o]

// ---------------- prepass: W fp32 [blk][o][b] -> fp16 [blk][b][o] ----------------
__global__ void conv_w_kernel(const float* __restrict__ v) {
    __shared__ float t[64][65];
    int blk = blockIdx.x;
    int tid = threadIdx.x;
    const float* src = v + (size_t)blk * 4096;
    #pragma unroll
    for (int k = 0; k < 16; k++) {
        int r = k * 4 + (tid >> 6);
        int c = tid & 63;
        t[r][c] = src[r * 64 + c];
    }
    __syncthreads();
    __half* dst = g_wt + (size_t)blk * 4096;
    #pragma unroll
    for (int k = 0; k < 16; k++) {
        int b = k * 4 + (tid >> 6);
        int o = tid & 63;
        dst[b * 64 + o] = __float2half(t[o][b]);
    }
}

// ---------------- PTX helpers ----------------
__device__ __forceinline__ uint32_t smem_u32(const void* p) {
    uint32_t a;
    asm("{ .reg .u64 t; cvta.to.shared.u64 t, %1; cvt.u32.u64 %0, t; }" : "=r"(a) : "l"(p));
    return a;
}
__device__ __forceinline__ void cp16(uint32_t s, const void* g) {
    asm volatile("cp.async.cg.shared.global [%0], [%1], 16;" :: "r"(s), "l"(g));
}
__device__ __forceinline__ void cp_commit() {
    asm volatile("cp.async.commit_group;");
}
__device__ __forceinline__ void ldsm4(uint32_t* d, uint32_t a) {
    asm volatile("ldmatrix.sync.aligned.m8n8.x4.shared.b16 {%0,%1,%2,%3}, [%4];"
                 : "=r"(d[0]), "=r"(d[1]), "=r"(d[2]), "=r"(d[3]) : "r"(a));
}
__device__ __forceinline__ void ldsm4t(uint32_t* d, uint32_t a) {
    asm volatile("ldmatrix.sync.aligned.m8n8.x4.trans.shared.b16 {%0,%1,%2,%3}, [%4];"
                 : "=r"(d[0]), "=r"(d[1]), "=r"(d[2]), "=r"(d[3]) : "r"(a));
}
__device__ __forceinline__ void mma16816(float* c, const uint32_t* a, const uint32_t* b) {
    asm volatile(
        "mma.sync.aligned.m16n8k16.row.col.f32.f16.f16.f32 "
        "{%0,%1,%2,%3}, {%4,%5,%6,%7}, {%8,%9}, {%0,%1,%2,%3};"
        : "+f"(c[0]), "+f"(c[1]), "+f"(c[2]), "+f"(c[3])
        : "r"(a[0]), "r"(a[1]), "r"(a[2]), "r"(a[3]), "r"(b[0]), "r"(b[1]));
}

// ---------------- main kernel: fused x convert + BSR GEMM ----------------
__global__ void __launch_bounds__(256, 1)
bsr_main_kernel(const float* __restrict__ x, const float* __restrict__ bias,
                const int* __restrict__ cols, float* __restrict__ out) {
    extern __shared__ char smem[];
    const uint32_t sb = smem_u32(smem);
    const int r  = blockIdx.x;   // row-block 0..63
    const int mt = blockIdx.y;   // batch tile 0..31
    const int tid = threadIdx.x;
    const int warp = tid >> 5;
    const int lane = tid & 31;
    const int wm = warp >> 1;    // 0..3 (m, 64 rows each)
    const int wn = warp & 1;     // 0..1 (n, 32 cols each)

    int cidx[BPR];
    #pragma unroll
    for (int j = 0; j < BPR; j++) cidx[j] = __ldg(&cols[r * BPR + j]);

    const float* xg = x + (size_t)mt * TM * INF;   // fp32 source
    const __half* wg = g_wt + (size_t)r * BPR * BS * BS;

    float acc[4][4][4];
    #pragma unroll
    for (int mi = 0; mi < 4; mi++)
        #pragma unroll
        for (int ni = 0; ni < 4; ni++)
            #pragma unroll
            for (int q = 0; q < 4; q++) acc[mi][ni][q] = 0.0f;

    // x fp32 prefetch registers: 8 fp16-chunks/thread -> 16 float4
    float4 xr[16];

    // thread -> (row, ch) map for x tiles: q = tid + k*256, row=q>>3, ch=q&7
    auto ldg_x = [&](int j) {
        const float* src = xg + cidx[j] * BS;
        #pragma unroll
        for (int k = 0; k < 8; k++) {
            int q = tid + k * 256;
            int row = q >> 3, ch = q & 7;
            const float4* p = (const float4*)(src + (size_t)row * INF + ch * 8);
            xr[2 * k]     = p[0];
            xr[2 * k + 1] = p[1];
        }
    };

    // convert xr -> fp16 smem buffer (j&1), swizzled
    auto cvt_sts_x = [&](int j) {
        char* xbuf = smem + (j & 1) * XT_BYTES;
        #pragma unroll
        for (int k = 0; k < 8; k++) {
            int q = tid + k * 256;
            int row = q >> 3, ch = q & 7;
            __half2 h0 = __floats2half2_rn(xr[2 * k].x, xr[2 * k].y);
            __half2 h1 = __floats2half2_rn(xr[2 * k].z, xr[2 * k].w);
            __half2 h2 = __floats2half2_rn(xr[2 * k + 1].x, xr[2 * k + 1].y);
            __half2 h3 = __floats2half2_rn(xr[2 * k + 1].z, xr[2 * k + 1].w);
            uint4 o;
            o.x = *(uint32_t*)&h0; o.y = *(uint32_t*)&h1;
            o.z = *(uint32_t*)&h2; o.w = *(uint32_t*)&h3;
            *(uint4*)(xbuf + row * 128 + ((ch ^ (row & 7)) << 4)) = o;
        }
    };

    // W cp.async issuer (one commit group per j)
    auto issue_w = [&](int j) {
        const char* wsrc = (const char*)(wg + (size_t)j * BS * BS);
        uint32_t ws = sb + W_BASE + (j % WSTAGES) * WT_BYTES;
        #pragma unroll
        for (int k = 0; k < 2; k++) {
            int q = tid + k * 256;          // 0..511
            int row = q >> 3, ch = q & 7;
            cp16(ws + row * 128 + ((ch ^ (row & 7)) << 4),
                 wsrc + row * 128 + ch * 16);
        }
        cp_commit();
    };

    ldg_x(0);
    issue_w(0);
    issue_w(1);
    issue_w(2);

    const int mat = lane >> 3;   // 0..3
    const int rl  = lane & 7;

    for (int j = 0; j < BPR; j++) {
        cvt_sts_x(j);            // regs (loaded last iter) -> smem buf j&1

        int rem = (BPR - 1) - j;
        if (rem >= 2)      asm volatile("cp.async.wait_group 2;");
        else if (rem == 1) asm volatile("cp.async.wait_group 1;");
        else               asm volatile("cp.async.wait_group 0;");
        __syncthreads();

        if (j + 1 < BPR) ldg_x(j + 1);   // overlap LDG latency with compute

        uint32_t xs = sb + (j & 1) * XT_BYTES;
        uint32_t ws = sb + W_BASE + (j % WSTAGES) * WT_BYTES;

        #pragma unroll
        for (int ks = 0; ks < 4; ks++) {
            uint32_t a[4][4];
            uint32_t b[4][2];
            #pragma unroll
            for (int mi = 0; mi < 4; mi++) {
                int row = wm * 64 + mi * 16 + (mat & 1) * 8 + rl;
                int ch = 2 * ks + (mat >> 1);
                ldsm4(a[mi], xs + row * 128 + ((ch ^ (row & 7)) << 4));
            }
            #pragma unroll
            for (int nh = 0; nh < 2; nh++) {
                int krow = ks * 16 + (mat & 1) * 8 + rl;
                int nch = wn * 4 + nh * 2 + (mat >> 1);
                uint32_t t[4];
                ldsm4t(t, ws + krow * 128 + ((nch ^ (krow & 7)) << 4));
                b[nh * 2][0] = t[0];     b[nh * 2][1] = t[1];
                b[nh * 2 + 1][0] = t[2]; b[nh * 2 + 1][1] = t[3];
            }
            #pragma unroll
            for (int mi = 0; mi < 4; mi++)
                #pragma unroll
                for (int ni = 0; ni < 4; ni++)
                    mma16816(acc[mi][ni], a[mi], b[ni]);
        }

        if (j + 3 < BPR) issue_w(j + 3);
    }

    // epilogue: add bias, write fp32
    #pragma unroll
    for (int mi = 0; mi < 4; mi++) {
        #pragma unroll
        for (int ni = 0; ni < 4; ni++) {
            int rr = mt * TM + wm * 64 + mi * 16 + (lane >> 2);
            int cc = r * BS + wn * 32 + ni * 8 + 2 * (lane & 3);
            float2 bv = *(const float2*)(bias + cc);
            float2 v0, v1;
            v0.x = acc[mi][ni][0] + bv.x;
            v0.y = acc[mi][ni][1] + bv.y;
            v1.x = acc[mi][ni][2] + bv.x;
            v1.y = acc[mi][ni][3] + bv.y;
            *(float2*)(out + (size_t)rr * OUTF + cc) = v0;
            *(float2*)(out + (size_t)(rr + 8) * OUTF + cc) = v1;
        }
    }
}

// ---------------- launch ----------------
extern "C" void kernel_launch(void* const* d_in, const int* in_sizes, int n_in,
                              void* d_out, int out_size) {
    const float* x      = (const float*)d_in[0];
    const float* values = (const float*)d_in[1];
    const float* bias   = (const float*)d_in[2];
    const int*   cols   = (const int*)d_in[3];
    float* out = (float*)d_out;

    conv_w_kernel<<<NBR * BPR, 256>>>(values);

    cudaFuncSetAttribute(bsr_main_kernel,
                         cudaFuncAttributeMaxDynamicSharedMemorySize, SMEM_SZ);
    bsr_main_kernel<<<dim3(NBR, NT_M), 256, SMEM_SZ>>>(x, bias, cols, out);
}

// round 8
// speedup vs baseline: 1.4566x; 1.4566x over previous
#include <cuda_runtime.h>
#include <cuda_fp16.h>
#include <cstdint>

#define BATCH 8192
#define INF   4096
#define OUTF  4096
#define BS    64
#define NBR   64
#define BPR   16
#define TM    256
#define NT_M  (BATCH / TM)          // 32
#define STAGES 4
#define XT_BYTES (TM * BS * 2)      // 32768
#define WT_BYTES (BS * BS * 2)      // 8192
#define W_BASE (STAGES * XT_BYTES)  // 131072
#define SMEM_SZ (W_BASE + STAGES * WT_BYTES)   // 163840

#define NCHUNK 8
#define MT_PER_CHUNK (NT_M / NCHUNK)            // 4
#define XBLK_PER_CHUNK ((BATCH / NCHUNK) * INF / 8 / 256)  // 2048

// Scratch (device globals; allocation-free)
__device__ __half g_xh[(size_t)BATCH * INF];            // fp16 x, row-major
__device__ __half g_wt[(size_t)NBR * BPR * BS * BS];    // fp16 W, [blk][b][o]

// ---------------- prepass: x fp32 -> fp16 (chunked) ----------------
__global__ void conv_x_kernel(const float* __restrict__ x, int chunk) {
    size_t i = (((size_t)chunk * XBLK_PER_CHUNK + blockIdx.x) * 256 + threadIdx.x) * 8;
    float4 a = *(const float4*)(x + i);
    float4 b = *(const float4*)(x + i + 4);
    __half2 h0 = __floats2half2_rn(a.x, a.y);
    __half2 h1 = __floats2half2_rn(a.z, a.w);
    __half2 h2 = __floats2half2_rn(b.x, b.y);
    __half2 h3 = __floats2half2_rn(b.z, b.w);
    uint4 o;
    o.x = *(uint32_t*)&h0; o.y = *(uint32_t*)&h1;
    o.z = *(uint32_t*)&h2; o.w = *(uint32_t*)&h3;
    *(uint4*)(g_xh + i) = o;
}

// ---------------- prepass: W fp32 [blk][o][b] -> fp16 [blk][b][o] ----------------
__global__ void conv_w_kernel(const float* __restrict__ v) {
    __shared__ float t[64][65];
    int blk = blockIdx.x;
    int tid = threadIdx.x;
    const float* src = v + (size_t)blk * 4096;
    #pragma unroll
    for (int k = 0; k < 16; k++) {
        int r = k * 4 + (tid >> 6);
        int c = tid & 63;
        t[r][c] = src[r * 64 + c];
    }
    __syncthreads();
    __half* dst = g_wt + (size_t)blk * 4096;
    #pragma unroll
    for (int k = 0; k < 16; k++) {
        int b = k * 4 + (tid >> 6);
        int o = tid & 63;
        dst[b * 64 + o] = __float2half(t[o][b]);
    }
}

// ---------------- PTX helpers ----------------
__device__ __forceinline__ uint32_t smem_u32(const void* p) {
    uint32_t a;
    asm("{ .reg .u64 t; cvta.to.shared.u64 t, %1; cvt.u32.u64 %0, t; }" : "=r"(a) : "l"(p));
    return a;
}
__device__ __forceinline__ void cp16(uint32_t s, const void* g) {
    asm volatile("cp.async.cg.shared.global [%0], [%1], 16;" :: "r"(s), "l"(g));
}
__device__ __forceinline__ void cp_commit() {
    asm volatile("cp.async.commit_group;");
}
__device__ __forceinline__ void ldsm4(uint32_t* d, uint32_t a) {
    asm volatile("ldmatrix.sync.aligned.m8n8.x4.shared.b16 {%0,%1,%2,%3}, [%4];"
                 : "=r"(d[0]), "=r"(d[1]), "=r"(d[2]), "=r"(d[3]) : "r"(a));
}
__device__ __forceinline__ void ldsm4t(uint32_t* d, uint32_t a) {
    asm volatile("ldmatrix.sync.aligned.m8n8.x4.trans.shared.b16 {%0,%1,%2,%3}, [%4];"
                 : "=r"(d[0]), "=r"(d[1]), "=r"(d[2]), "=r"(d[3]) : "r"(a));
}
__device__ __forceinline__ void mma16816(float* c, const uint32_t* a, const uint32_t* b) {
    asm volatile(
        "mma.sync.aligned.m16n8k16.row.col.f32.f16.f16.f32 "
        "{%0,%1,%2,%3}, {%4,%5,%6,%7}, {%8,%9}, {%0,%1,%2,%3};"
        : "+f"(c[0]), "+f"(c[1]), "+f"(c[2]), "+f"(c[3])
        : "r"(a[0]), "r"(a[1]), "r"(a[2]), "r"(a[3]), "r"(b[0]), "r"(b[1]));
}

// ---------------- main kernel (R3 form, pure f32 accum) ----------------
__global__ void __launch_bounds__(256, 1)
bsr_main_kernel(const float* __restrict__ bias, const int* __restrict__ cols,
                float* __restrict__ out, int mt_base) {
    extern __shared__ char smem[];
    const uint32_t sb = smem_u32(smem);
    const int r  = blockIdx.x;              // row-block 0..63
    const int mt = mt_base + blockIdx.y;    // batch tile
    const int tid = threadIdx.x;
    const int warp = tid >> 5;
    const int lane = tid & 31;
    const int wm = warp >> 1;    // 0..3 (m, 64 rows each)
    const int wn = warp & 1;     // 0..1 (n, 32 cols each)

    int cidx[BPR];
    #pragma unroll
    for (int j = 0; j < BPR; j++) cidx[j] = __ldg(&cols[r * BPR + j]);

    const __half* xg = g_xh + (size_t)mt * TM * INF;
    const __half* wg = g_wt + (size_t)r * BPR * BS * BS;

    float acc[4][4][4];
    #pragma unroll
    for (int mi = 0; mi < 4; mi++)
        #pragma unroll
        for (int ni = 0; ni < 4; ni++)
            #pragma unroll
            for (int q = 0; q < 4; q++) acc[mi][ni][q] = 0.0f;

    auto issue = [&](int j) {
        int s = j % STAGES;
        int c = cidx[j];
        const char* xsrc = (const char*)(xg + (size_t)c * BS);
        uint32_t xs = sb + s * XT_BYTES;
        #pragma unroll
        for (int k = 0; k < 8; k++) {
            int q = tid + k * 256;          // 0..2047
            int row = q >> 3, ch = q & 7;
            cp16(xs + row * 128 + ((ch ^ (row & 7)) << 4),
                 xsrc + (size_t)row * (INF * 2) + ch * 16);
        }
        const char* wsrc = (const char*)(wg + (size_t)j * BS * BS);
        uint32_t ws = sb + W_BASE + s * WT_BYTES;
        #pragma unroll
        for (int k = 0; k < 2; k++) {
            int q = tid + k * 256;          // 0..511
            int row = q >> 3, ch = q & 7;
            cp16(ws + row * 128 + ((ch ^ (row & 7)) << 4),
                 wsrc + row * 128 + ch * 16);
        }
        cp_commit();
    };

    issue(0);
    issue(1);
    issue(2);

    const int mat = lane >> 3;   // 0..3
    const int rl  = lane & 7;

    for (int j = 0; j < BPR; j++) {
        int rem = (BPR - 1) - j;
        if (rem >= 2)      asm volatile("cp.async.wait_group 2;");
        else if (rem == 1) asm volatile("cp.async.wait_group 1;");
        else               asm volatile("cp.async.wait_group 0;");
        __syncthreads();

        uint32_t xs = sb + (j % STAGES) * XT_BYTES;
        uint32_t ws = sb + W_BASE + (j % STAGES) * WT_BYTES;

        #pragma unroll
        for (int ks = 0; ks < 4; ks++) {
            uint32_t a[4][4];
            uint32_t b[4][2];
            #pragma unroll
            for (int mi = 0; mi < 4; mi++) {
                int row = wm * 64 + mi * 16 + (mat & 1) * 8 + rl;
                int ch = 2 * ks + (mat >> 1);
                ldsm4(a[mi], xs + row * 128 + ((ch ^ (row & 7)) << 4));
            }
            #pragma unroll
            for (int nh = 0; nh < 2; nh++) {
                int krow = ks * 16 + (mat & 1) * 8 + rl;
                int nch = wn * 4 + nh * 2 + (mat >> 1);
                uint32_t t[4];
                ldsm4t(t, ws + krow * 128 + ((nch ^ (krow & 7)) << 4));
                b[nh * 2][0] = t[0];     b[nh * 2][1] = t[1];
                b[nh * 2 + 1][0] = t[2]; b[nh * 2 + 1][1] = t[3];
            }
            #pragma unroll
            for (int mi = 0; mi < 4; mi++)
                #pragma unroll
                for (int ni = 0; ni < 4; ni++)
                    mma16816(acc[mi][ni], a[mi], b[ni]);
        }

        if (j + 3 < BPR) issue(j + 3);
    }

    // epilogue: add bias, write fp32
    #pragma unroll
    for (int mi = 0; mi < 4; mi++) {
        #pragma unroll
        for (int ni = 0; ni < 4; ni++) {
            int rr = mt * TM + wm * 64 + mi * 16 + (lane >> 2);
            int cc = r * BS + wn * 32 + ni * 8 + 2 * (lane & 3);
            float2 bv = *(const float2*)(bias + cc);
            float2 v0, v1;
            v0.x = acc[mi][ni][0] + bv.x;
            v0.y = acc[mi][ni][1] + bv.y;
            v1.x = acc[mi][ni][2] + bv.x;
            v1.y = acc[mi][ni][3] + bv.y;
            *(float2*)(out + (size_t)rr * OUTF + cc) = v0;
            *(float2*)(out + (size_t)(rr + 8) * OUTF + cc) = v1;
        }
    }
}

// ---------------- stream/event setup (global ctor: pre-checkpoint) ----------------
struct GraphResources {
    cudaStream_t sx;                 // conversion stream
    cudaStream_t sm[NCHUNK];         // one stream per main chunk
    cudaEvent_t root;
    cudaEvent_t evx[NCHUNK];         // x chunk ready
    cudaEvent_t evm[NCHUNK];         // main chunk done
    GraphResources() {
        cudaStreamCreateWithFlags(&sx, cudaStreamNonBlocking);
        for (int i = 0; i < NCHUNK; i++)
            cudaStreamCreateWithFlags(&sm[i], cudaStreamNonBlocking);
        cudaEventCreateWithFlags(&root, cudaEventDisableTiming);
        for (int i = 0; i < NCHUNK; i++) {
            cudaEventCreateWithFlags(&evx[i], cudaEventDisableTiming);
            cudaEventCreateWithFlags(&evm[i], cudaEventDisableTiming);
        }
        cudaFuncSetAttribute(bsr_main_kernel,
                             cudaFuncAttributeMaxDynamicSharedMemorySize, SMEM_SZ);
    }
};
static GraphResources g_res;

// ---------------- launch ----------------
extern "C" void kernel_launch(void* const* d_in, const int* in_sizes, int n_in,
                              void* d_out, int out_size) {
    const float* x      = (const float*)d_in[0];
    const float* values = (const float*)d_in[1];
    const float* bias   = (const float*)d_in[2];
    const int*   cols   = (const int*)d_in[3];
    float* out = (float*)d_out;

    cudaFuncSetAttribute(bsr_main_kernel,
                         cudaFuncAttributeMaxDynamicSharedMemorySize, SMEM_SZ);

    // Fork from the capture stream.
    cudaEventRecord(g_res.root, 0);
    cudaStreamWaitEvent(g_res.sx, g_res.root, 0);

    // Conversion stream: W first (mains need it), then x chunk by chunk.
    conv_w_kernel<<<NBR * BPR, 256, 0, g_res.sx>>>(values);
    for (int c = 0; c < NCHUNK; c++) {
        conv_x_kernel<<<XBLK_PER_CHUNK, 256, 0, g_res.sx>>>(x, c);
        cudaEventRecord(g_res.evx[c], g_res.sx);
    }

    // Main chunks: each on its OWN stream -> concurrent, tails overlap.
    for (int c = 0; c < NCHUNK; c++) {
        cudaStreamWaitEvent(g_res.sm[c], g_res.evx[c], 0);
        bsr_main_kernel<<<dim3(NBR, MT_PER_CHUNK), 256, SMEM_SZ, g_res.sm[c]>>>(
            bias, cols, out, c * MT_PER_CHUNK);
        cudaEventRecord(g_res.evm[c], g_res.sm[c]);
    }

    // Join back to the capture stream.
    for (int c = 0; c < NCHUNK; c++)
        cudaStreamWaitEvent(0, g_res.evm[c], 0);
}